// round 12
// baseline (speedup 1.0000x reference)
#include <cuda_runtime.h>
#include <math.h>

// input:  (B=2, T=2048, V=32000) f32 ; target: (2, 2048) int32 ; out: scalar f32
// ct_len = 512, win = 256
#define B_DIM 2
#define T_DIM 2048
#define V_DIM 32000
#define CT_LEN 512
#define WIN 256
#define ROWS (B_DIM * CT_LEN)      // 1024
#define IGNORE_INDEX (-100)
#define PAD_ID 0

#define R_PER_WARP 4
#define CTA_THREADS 32
#define GRID_CTAS (ROWS / R_PER_WARP)         // 256
#define NPL (WIN / 32)                        // 8 negatives per lane per row

// Allocation-free scratch (every element rewritten each call; counter self-resets)
__device__ float        g_row_loss[ROWS];
__device__ float        g_row_valid[ROWS];
__device__ unsigned int g_done = 0u;

__device__ __forceinline__ void prefetch_l2(const void* p) {
    asm volatile("prefetch.global.L2 [%0];" :: "l"(p));
}

__global__ __launch_bounds__(CTA_THREADS, 16)
void ctl_pipe_kernel(const float* __restrict__ input,
                     const int* __restrict__ target,
                     float* __restrict__ out)
{
    const int lane = threadIdx.x;
    const int row0 = blockIdx.x * R_PER_WARP;   // 4 consecutive rows, same b
    const int b    = row0 >> 9;
    const int i0   = row0 & (CT_LEN - 1);
    const int tbase = b * T_DIM;

    // ---- phase 0: ALL target loads for 4 rows (coalesced, one latency) ----
    int tpos[R_PER_WARP];
    int tj[R_PER_WARP][NPL];
    #pragma unroll
    for (int r = 0; r < R_PER_WARP; r++) {
        const int i = i0 + r;
        tpos[r] = __ldg(&target[tbase + i]);
        #pragma unroll
        for (int k = 0; k < NPL; k++) {
            const int j = i - WIN + k * 32 + lane;
            tj[r][k] = (j >= 0) ? __ldg(&target[tbase + j]) : PAD_ID;
        }
    }

    // ---- indices + row bases ----
    long long lbase[R_PER_WARP];
    int ts[R_PER_WARP];
    int idx[R_PER_WARP][NPL];
    #pragma unroll
    for (int r = 0; r < R_PER_WARP; r++) {
        const int i = i0 + r;
        lbase[r] = ((long long)(tbase + i)) * V_DIM;
        int t = tpos[r];
        int s = (t != IGNORE_INDEX) ? t : PAD_ID;
        ts[r] = s < 0 ? 0 : (s >= V_DIM ? V_DIM - 1 : s);
        #pragma unroll
        for (int k = 0; k < NPL; k++) {
            int c = tj[r][k];
            idx[r][k] = c < 0 ? 0 : (c >= V_DIM ? V_DIM - 1 : c);
        }
    }

    // ---- phase 1: fire-and-forget L2 prefetch for rows 1..3 (NOT row 0).
    // Row 0's demand-latency (~600cyc) is the cover time these need to land.
    #pragma unroll
    for (int r = 1; r < R_PER_WARP; r++) {
        prefetch_l2(&input[lbase[r] + ts[r]]);
        #pragma unroll
        for (int k = 0; k < NPL; k++)
            prefetch_l2(&input[lbase[r] + idx[r][k]]);
    }

    // ---- phase 2: demand-process rows in order; rows 1..3 should L2-hit ----
    #pragma unroll
    for (int r = 0; r < R_PER_WARP; r++) {
        const int vrow = (tpos[r] != IGNORE_INDEX);
        const float pos = __ldg(&input[lbase[r] + ts[r]]);
        float nv[NPL];
        #pragma unroll
        for (int k = 0; k < NPL; k++)
            nv[k] = __ldg(&input[lbase[r] + idx[r][k]]);

        float e = 0.0f;
        #pragma unroll
        for (int k = 0; k < NPL; k++) {
            if (tj[r][k] != PAD_ID)                // j<0 lanes carry PAD -> excluded
                e += __expf(nv[k] - pos);
        }
        #pragma unroll
        for (int o = 16; o > 0; o >>= 1)
            e += __shfl_down_sync(0xffffffffu, e, o);

        if (lane == 0) {
            g_row_loss[row0 + r]  = vrow ? log1pf(e) : 0.0f;
            g_row_valid[row0 + r] = (float)vrow;
        }
    }

    // ---- ticket: last CTA (1 warp) finalizes ----
    __shared__ int s_last;
    if (lane == 0) {
        __threadfence();
        unsigned int ticket = atomicAdd(&g_done, 1u);
        s_last = (ticket == (unsigned int)(GRID_CTAS - 1));
    }
    __syncwarp();
    if (s_last) {
        float l = 0.0f, v = 0.0f;
        #pragma unroll 4
        for (int k = 0; k < ROWS / 32; k++) {
            l += g_row_loss[lane + k * 32];
            v += g_row_valid[lane + k * 32];
        }
        #pragma unroll
        for (int o = 16; o > 0; o >>= 1) {
            l += __shfl_down_sync(0xffffffffu, l, o);
            v += __shfl_down_sync(0xffffffffu, v, o);
        }
        if (lane == 0) {
            out[0] = l / fmaxf(v, 1.0f);
            g_done = 0u;                       // reset for next graph replay
        }
    }
}

extern "C" void kernel_launch(void* const* d_in, const int* in_sizes, int n_in,
                              void* d_out, int out_size)
{
    const float* input  = (const float*)d_in[0];
    const int*   target = (const int*)d_in[1];
    float*       out    = (float*)d_out;

    (void)in_sizes; (void)n_in; (void)out_size;

    ctl_pipe_kernel<<<GRID_CTAS, CTA_THREADS>>>(input, target, out);
}

// round 13
// speedup vs baseline: 1.4669x; 1.4669x over previous
#include <cuda_runtime.h>
#include <math.h>

// input:  (B=2, T=2048, V=32000) f32 ; target: (2, 2048) int32 ; out: scalar f32
// ct_len = 512, win = 256
#define B_DIM 2
#define T_DIM 2048
#define V_DIM 32000
#define CT_LEN 512
#define WIN 256
#define ROWS (B_DIM * CT_LEN)      // 1024
#define IGNORE_INDEX (-100)
#define PAD_ID 0

#define WARPS_PER_CTA 8
#define CTA_THREADS (WARPS_PER_CTA * 32)      // 256
#define GRID_CTAS (ROWS / WARPS_PER_CTA)      // 128
#define NPL (WIN / 32)                        // 8 negatives per lane
#define NHALF (NPL / 2)                       // 4

// Allocation-free scratch (every element rewritten each call; counter self-resets)
__device__ float        g_row_loss[ROWS];
__device__ float        g_row_valid[ROWS];
__device__ unsigned int g_done = 0u;

__device__ __forceinline__ void prefetch_l2(const void* p) {
    asm volatile("prefetch.global.L2 [%0];" :: "l"(p));
}

__global__ __launch_bounds__(CTA_THREADS, 8)
void ctl_split_kernel(const float* __restrict__ input,
                      const int* __restrict__ target,
                      float* __restrict__ out)
{
    const int tid  = threadIdx.x;
    const int lane = tid & 31;
    const int w    = tid >> 5;
    const int row  = blockIdx.x * WARPS_PER_CTA + w;  // 0..1023
    const int b    = row >> 9;
    const int i    = row & (CT_LEN - 1);

    const int tbase = b * T_DIM;
    const long long lbase = ((long long)(tbase + i)) * V_DIM;

    // --- targets (coalesced, L2-hot after first wave) ---
    const int t = __ldg(&target[tbase + i]);
    int tj[NPL];
    #pragma unroll
    for (int k = 0; k < NPL; k++) {
        const int j = i - WIN + k * 32 + lane;
        tj[k] = (j >= 0) ? __ldg(&target[tbase + j]) : PAD_ID;
    }

    const int vrow = (t != IGNORE_INDEX);
    int ts = vrow ? t : PAD_ID;
    ts = ts < 0 ? 0 : (ts >= V_DIM ? V_DIM - 1 : ts);

    int idx[NPL];
    #pragma unroll
    for (int k = 0; k < NPL; k++) {
        int c = tj[k];
        idx[k] = c < 0 ? 0 : (c >= V_DIM ? V_DIM - 1 : c);
    }

    // --- phase A: fire-and-forget L2 prefetch for the SECOND half.
    // No MSHR held -> over-subscribes the DRAM queue beyond the demand cap.
    #pragma unroll
    for (int k = NHALF; k < NPL; k++)
        prefetch_l2(&input[lbase + idx[k]]);

    // --- phase B: demand loads for first half + pos (~600cyc at DRAM).
    // This latency is the head start the phase-A prefetches need.
    const float pos = __ldg(&input[lbase + ts]);
    float nv[NPL];
    #pragma unroll
    for (int k = 0; k < NHALF; k++)
        nv[k] = __ldg(&input[lbase + idx[k]]);

    // --- phase C: demand loads for second half — L2 hits if DRAM had headroom.
    #pragma unroll
    for (int k = NHALF; k < NPL; k++)
        nv[k] = __ldg(&input[lbase + idx[k]]);

    // --- compute + warp reduction ---
    float e = 0.0f;
    #pragma unroll
    for (int k = 0; k < NPL; k++) {
        if (tj[k] != PAD_ID)                      // j<0 lanes carry PAD -> excluded
            e += __expf(nv[k] - pos);
    }
    #pragma unroll
    for (int o = 16; o > 0; o >>= 1)
        e += __shfl_down_sync(0xffffffffu, e, o);

    if (lane == 0) {
        g_row_loss[row]  = vrow ? log1pf(e) : 0.0f;
        g_row_valid[row] = (float)vrow;
    }

    // --- last-CTA final reduction ---
    __shared__ int s_last;
    __syncthreads();
    if (tid == 0) {
        __threadfence();
        unsigned int ticket = atomicAdd(&g_done, 1u);
        s_last = (ticket == (unsigned int)(GRID_CTAS - 1));
    }
    __syncthreads();

    if (s_last) {
        float l = 0.0f, v = 0.0f;
        #pragma unroll
        for (int k = 0; k < ROWS / CTA_THREADS; k++) {
            l += g_row_loss[tid + k * CTA_THREADS];
            v += g_row_valid[tid + k * CTA_THREADS];
        }
        #pragma unroll
        for (int o = 16; o > 0; o >>= 1) {
            l += __shfl_down_sync(0xffffffffu, l, o);
            v += __shfl_down_sync(0xffffffffu, v, o);
        }
        __shared__ float sl[WARPS_PER_CTA];
        __shared__ float sv[WARPS_PER_CTA];
        if (lane == 0) { sl[w] = l; sv[w] = v; }
        __syncthreads();
        if (tid == 0) {
            float l2 = 0.0f, v2 = 0.0f;
            #pragma unroll
            for (int q = 0; q < WARPS_PER_CTA; q++) { l2 += sl[q]; v2 += sv[q]; }
            out[0] = l2 / fmaxf(v2, 1.0f);
            g_done = 0u;                       // reset for next graph replay
        }
    }
}

extern "C" void kernel_launch(void* const* d_in, const int* in_sizes, int n_in,
                              void* d_out, int out_size)
{
    const float* input  = (const float*)d_in[0];
    const int*   target = (const int*)d_in[1];
    float*       out    = (float*)d_out;

    (void)in_sizes; (void)n_in; (void)out_size;

    ctl_split_kernel<<<GRID_CTAS, CTA_THREADS>>>(input, target, out);
}